// round 6
// baseline (speedup 1.0000x reference)
#include <cuda_runtime.h>
#include <cstdint>
#include <cstddef>

// ---------------------------------------------------------------------------
// ReLU-LSTM: S=2048, B=128, H=256, IN=256, L=2; a single (h,c) state threads
// through both layers and time (faithful to the reference).
//
//   prologue_kernel: P[t,b,c'] = x_t @ w_ih0^T + b_ih0 + b_hh0 (all t parallel)
//                    column-permuted c' = ht*64 + hl*4 + gate; also copies
//                    h0[0] -> g_hbuf[0] and resets the grid barrier.
//   lstm_kernel:     persistent 128-CTA kernel; 2048 steps x 2 layer phases.
//                    Layer 1 uses W1 = w_ih1 + w_hh1 (input == recurrent h).
// ---------------------------------------------------------------------------

#define S_    2048
#define B_    128
#define H_    256
#define IN_   256
#define GH_   1024        // 4*H gate columns
#define NCTA  128         // 8 batch-tiles x 16 h-tiles
#define NTHR  128
#define WPAD  260         // padded row stride (floats) for 256-float rows

#define OUT_Y  ((size_t)S_ * B_ * H_)                // per-step outputs
#define HY_OFF (OUT_Y)                               // hy [1,2,B,H]
#define CY_OFF (OUT_Y + 2ull * B_ * H_)              // cy [1,2,B,H]

// Static device scratch (no allocations anywhere).
__device__ float    g_P[(size_t)S_ * B_ * GH_];      // 1 GB precomputed proj
__device__ float    g_hbuf[2][B_ * H_];              // double-buffered h
__device__ unsigned g_bar;                           // grid barrier counter

__device__ __forceinline__ float sigf(float x) { return 1.0f / (1.0f + __expf(-x)); }

// 16(batch) x 64(gatecol) x 256(k) micro-GEMM piece: this thread accumulates
// 2 batch rows x 4 gates. wb points at weight row hl of gate 0; gate g lives
// at +g*16*WPAD rows.
__device__ __forceinline__ void gemm_tile(const float* __restrict__ wb,
                                          const float* __restrict__ a0p,
                                          const float* __restrict__ a1p,
                                          float acc[2][4]) {
#pragma unroll 8
  for (int k = 0; k < 256; k += 4) {
    float4 a0 = *(const float4*)(a0p + k);
    float4 a1 = *(const float4*)(a1p + k);
#pragma unroll
    for (int g = 0; g < 4; ++g) {
      float4 w = *(const float4*)(wb + g * (16 * WPAD) + k);
      acc[0][g] = fmaf(a0.x, w.x, acc[0][g]);
      acc[0][g] = fmaf(a0.y, w.y, acc[0][g]);
      acc[0][g] = fmaf(a0.z, w.z, acc[0][g]);
      acc[0][g] = fmaf(a0.w, w.w, acc[0][g]);
      acc[1][g] = fmaf(a1.x, w.x, acc[1][g]);
      acc[1][g] = fmaf(a1.y, w.y, acc[1][g]);
      acc[1][g] = fmaf(a1.z, w.z, acc[1][g]);
      acc[1][g] = fmaf(a1.w, w.w, acc[1][g]);
    }
  }
}

// ---------------------------------------------------------------------------
// Prologue: grid = (16 h-tiles, 2048 blocks of 128 flattened (t,b) rows).
// ---------------------------------------------------------------------------
__global__ void __launch_bounds__(NTHR) prologue_kernel(
    const float* __restrict__ x,   const float* __restrict__ h0,
    const float* __restrict__ w_ih, const float* __restrict__ b_ih,
    const float* __restrict__ b_hh) {
  extern __shared__ float sm[];
  float* sW = sm;              // 64 x WPAD
  float* sA = sm + 64 * WPAD;  // 16 x WPAD
  const int tid = threadIdx.x;
  const int ht  = blockIdx.x;

  if (blockIdx.y == 0) {
    if (blockIdx.x == 0 && tid == 0) g_bar = 0u;
    // copy h0[0] (first B*H elements) into buffer 0
    int gtid = blockIdx.x * NTHR + tid;
    for (int i = gtid; i < B_ * H_; i += 16 * NTHR) g_hbuf[0][i] = h0[i];
  }

  // Load w_ih[0] slice, gate-major rows r = g*16 + hl (float4 vectorized).
  for (int idx = tid; idx < 64 * 64; idx += NTHR) {
    int r = idx >> 6, kq = idx & 63;
    int g = r >> 4, hl2 = r & 15;
    int gcol = g * 256 + ht * 16 + hl2;
    *(float4*)&sW[r * WPAD + kq * 4] =
        __ldg((const float4*)(w_ih + (size_t)gcol * IN_) + kq);
  }
  const int hl = tid & 15, bp = tid >> 4;
  float bias[4];
#pragma unroll
  for (int g = 0; g < 4; ++g) {
    int gcol = g * 256 + ht * 16 + hl;
    bias[g] = b_ih[gcol] + b_hh[gcol];
  }
  const float* wb = sW + hl * WPAD;

  for (int sub = 0; sub < 8; ++sub) {
    size_t rows0 = (size_t)blockIdx.y * 128 + sub * 16;
    __syncthreads();  // weights ready (sub 0) / previous GEMM readers done
    const float4* xs = (const float4*)(x + rows0 * IN_);
    for (int idx = tid; idx < 16 * 64; idx += NTHR) {
      int rr = idx >> 6, kq = idx & 63;
      *(float4*)&sA[rr * WPAD + kq * 4] = __ldg(xs + rr * 64 + kq);
    }
    __syncthreads();
    float acc[2][4] = {{bias[0], bias[1], bias[2], bias[3]},
                       {bias[0], bias[1], bias[2], bias[3]}};
    gemm_tile(wb, sA + (2 * bp) * WPAD, sA + (2 * bp + 1) * WPAD, acc);
#pragma unroll
    for (int bi = 0; bi < 2; ++bi) {
      size_t r = rows0 + 2 * bp + bi;
      float4 v = make_float4(acc[bi][0], acc[bi][1], acc[bi][2], acc[bi][3]);
      __stcs((float4*)&g_P[r * GH_ + ht * 64 + hl * 4], v);
    }
  }
}

// Monotonic grid barrier: g_bar reset by prologue each launch; target grows
// by NCTA per barrier. __threadfence (cumulative) publishes this CTA's global
// writes; acquire-poll orders the observations.
__device__ __forceinline__ void grid_barrier(unsigned target) {
  __syncthreads();
  if (threadIdx.x == 0) {
    __threadfence();
    atomicAdd(&g_bar, 1u);
    unsigned v;
    do {
      asm volatile("ld.acquire.gpu.b32 %0, [%1];" : "=r"(v) : "l"(&g_bar) : "memory");
    } while (v < target);
  }
  __syncthreads();
}

// ---------------------------------------------------------------------------
// Persistent recurrent kernel: 128 CTAs (8 bt x 16 ht) x 128 threads.
// Thread (hl = tid&15, bp = tid>>4) owns cells (b0, hglob), (b0+1, hglob)
// with b0 = bt*16 + 2*bp, hglob = ht*16 + hl; c-state in registers.
// ---------------------------------------------------------------------------
__global__ void __launch_bounds__(NTHR, 1) lstm_kernel(
    const float* __restrict__ c0,
    const float* __restrict__ w_ih, const float* __restrict__ b_ih,
    const float* __restrict__ w_hh, const float* __restrict__ b_hh,
    float* __restrict__ out) {
  extern __shared__ float sm[];
  float* sW0 = sm;               // layer-0 w_hh slice, 64 x WPAD
  float* sW1 = sm + 64 * WPAD;   // layer-1 (w_ih1+w_hh1) slice, 64 x WPAD
  float* sA  = sm + 128 * WPAD;  // h staging, 16 x WPAD
  const int tid = threadIdx.x;
  const int bt  = blockIdx.x >> 4;   // 0..7
  const int ht  = blockIdx.x & 15;   // 0..15
  const int hl  = tid & 15, bp = tid >> 4;
  const int b0  = bt * 16 + 2 * bp;
  const int hglob = ht * 16 + hl;

  // Resident weights (loaded once). Gate-major rows r = g*16 + hl2.
  for (int idx = tid; idx < 64 * 64; idx += NTHR) {
    int r = idx >> 6, kq = idx & 63;
    int g = r >> 4, hl2 = r & 15;
    int gcol = g * 256 + ht * 16 + hl2;
    float4 w0 = __ldg((const float4*)(w_hh + (size_t)gcol * H_) + kq);
    *(float4*)&sW0[r * WPAD + kq * 4] = w0;
    float4 wa = __ldg((const float4*)(w_ih + (size_t)(GH_ + gcol) * IN_) + kq);
    float4 wb4 = __ldg((const float4*)(w_hh + (size_t)(GH_ + gcol) * H_) + kq);
    *(float4*)&sW1[r * WPAD + kq * 4] =
        make_float4(wa.x + wb4.x, wa.y + wb4.y, wa.z + wb4.z, wa.w + wb4.w);
  }
  float bias1[4];
#pragma unroll
  for (int g = 0; g < 4; ++g) {
    int gcol = g * 256 + ht * 16 + hl;
    bias1[g] = b_ih[GH_ + gcol] + b_hh[GH_ + gcol];
  }
  const float* wb0 = sW0 + hl * WPAD;
  const float* wb1 = sW1 + hl * WPAD;
  const float* a0p = sA + (2 * bp) * WPAD;
  const float* a1p = a0p + WPAD;

  float c[2];
#pragma unroll
  for (int bi = 0; bi < 2; ++bi) c[bi] = c0[(size_t)(b0 + bi) * H_ + hglob];

  unsigned target = NCTA;

  for (int t = 0; t < S_; ++t) {
    // ---------------- Phase A: layer 0 (reads buf0, writes buf1) ----------
    float4 p[2];
#pragma unroll
    for (int bi = 0; bi < 2; ++bi) {
      size_t r = (size_t)t * B_ + b0 + bi;
      p[bi] = __ldcs((const float4*)&g_P[r * GH_ + ht * 64 + hl * 4]);
    }
    for (int idx = tid; idx < 16 * 64; idx += NTHR) {
      int rr = idx >> 6, kq = idx & 63;
      *(float4*)&sA[rr * WPAD + kq * 4] =
          __ldcg((const float4*)&g_hbuf[0][(size_t)(bt * 16 + rr) * H_] + kq);
    }
    __syncthreads();
    {
      float acc[2][4] = {{p[0].x, p[0].y, p[0].z, p[0].w},
                         {p[1].x, p[1].y, p[1].z, p[1].w}};
      gemm_tile(wb0, a0p, a1p, acc);
#pragma unroll
      for (int bi = 0; bi < 2; ++bi) {
        float ig = acc[bi][0], fg = acc[bi][1], cg = acc[bi][2], og = acc[bi][3];
        c[bi] = sigf(fg) * c[bi] + sigf(ig) * fmaxf(cg, 0.0f);
        float h = sigf(og) * fmaxf(c[bi], 0.0f);
        __stcg(&g_hbuf[1][(size_t)(b0 + bi) * H_ + hglob], h);
        if (t == S_ - 1) {
          out[HY_OFF + (size_t)(b0 + bi) * H_ + hglob] = h;
          out[CY_OFF + (size_t)(b0 + bi) * H_ + hglob] = c[bi];
        }
      }
    }
    grid_barrier(target); target += NCTA;

    // ---------------- Phase B: layer 1 (reads buf1, writes buf0) ----------
    for (int idx = tid; idx < 16 * 64; idx += NTHR) {
      int rr = idx >> 6, kq = idx & 63;
      *(float4*)&sA[rr * WPAD + kq * 4] =
          __ldcg((const float4*)&g_hbuf[1][(size_t)(bt * 16 + rr) * H_] + kq);
    }
    __syncthreads();
    {
      float acc[2][4] = {{bias1[0], bias1[1], bias1[2], bias1[3]},
                         {bias1[0], bias1[1], bias1[2], bias1[3]}};
      gemm_tile(wb1, a0p, a1p, acc);
#pragma unroll
      for (int bi = 0; bi < 2; ++bi) {
        float ig = acc[bi][0], fg = acc[bi][1], cg = acc[bi][2], og = acc[bi][3];
        c[bi] = sigf(fg) * c[bi] + sigf(ig) * fmaxf(cg, 0.0f);
        float h = sigf(og) * fmaxf(c[bi], 0.0f);
        __stcg(&g_hbuf[0][(size_t)(b0 + bi) * H_ + hglob], h);
        __stcs(&out[(size_t)t * B_ * H_ + (size_t)(b0 + bi) * H_ + hglob], h);
        if (t == S_ - 1) {
          out[HY_OFF + (size_t)B_ * H_ + (size_t)(b0 + bi) * H_ + hglob] = h;
          out[CY_OFF + (size_t)B_ * H_ + (size_t)(b0 + bi) * H_ + hglob] = c[bi];
        }
      }
    }
    grid_barrier(target); target += NCTA;
  }
}

extern "C" void kernel_launch(void* const* d_in, const int* in_sizes, int n_in,
                              void* d_out, int out_size) {
  const float* x    = (const float*)d_in[0];
  const float* h0   = (const float*)d_in[1];
  const float* c0   = (const float*)d_in[2];
  const float* w_ih = (const float*)d_in[3];
  const float* b_ih = (const float*)d_in[4];
  const float* w_hh = (const float*)d_in[5];
  const float* b_hh = (const float*)d_in[6];
  float* out = (float*)d_out;

  const int PRO_SMEM  = 80  * WPAD * sizeof(float);   //  83,200 B
  const int LSTM_SMEM = 144 * WPAD * sizeof(float);   // 149,760 B
  static bool attr_done = false;
  if (!attr_done) {
    cudaFuncSetAttribute(prologue_kernel,
                         cudaFuncAttributeMaxDynamicSharedMemorySize, PRO_SMEM);
    cudaFuncSetAttribute(lstm_kernel,
                         cudaFuncAttributeMaxDynamicSharedMemorySize, LSTM_SMEM);
    attr_done = true;
  }

  dim3 pgrid(16, (S_ * B_) / 128);  // (h-tiles, 128-row blocks)
  prologue_kernel<<<pgrid, NTHR, PRO_SMEM>>>(x, h0, w_ih, b_ih, b_hh);
  lstm_kernel<<<NCTA, NTHR, LSTM_SMEM>>>(c0, w_ih, b_ih, w_hh, b_hh, out);
}

// round 7
// speedup vs baseline: 1.0090x; 1.0090x over previous
#include <cuda_runtime.h>
#include <cstdint>
#include <cstddef>

// ---------------------------------------------------------------------------
// ReLU-LSTM: S=2048, B=128, H=256, IN=256, L=2; one (h,c) state threads
// through both layers and time.
//
//   prologue_kernel: P[t,b,c'] = x_t @ w_ih0^T + b_ih0 + b_hh0 (all t parallel)
//                    column-permuted c' = ht*64 + hl*4 + gate; also copies
//                    h0[0] -> g_hbuf[0] and resets the per-bt barriers.
//   lstm_kernel:     persistent 128-CTA kernel; 2048 steps x 2 layer phases.
//                    Layer 1 uses W1 = w_ih1 + w_hh1 (input == recurrent h).
//
// R6 changes: (a) fma.rn.f32x2 packed GEMM (2 MACs/issue, even/odd-k split
// accumulators), (b) per-bt 16-CTA barriers instead of one 128-CTA barrier,
// (c) arrive/wait split with P-prefetch and out-stores inside the barrier
// window.
// ---------------------------------------------------------------------------

#define S_    2048
#define B_    128
#define H_    256
#define IN_   256
#define GH_   1024        // 4*H gate columns
#define NCTA  128         // 8 batch-tiles x 16 h-tiles
#define NTHR  128
#define WPAD  260         // padded row stride (floats); 260 % 4 == 0 (16B ok)

#define OUT_Y  ((size_t)S_ * B_ * H_)                // per-step outputs
#define HY_OFF (OUT_Y)                               // hy [1,2,B,H]
#define CY_OFF (OUT_Y + 2ull * B_ * H_)              // cy [1,2,B,H]

typedef unsigned long long ull;

// Static device scratch (no allocations anywhere).
__device__ float    g_P[(size_t)S_ * B_ * GH_];      // 1 GB precomputed proj
__device__ float    g_hbuf[2][B_ * H_];              // double-buffered h
__device__ unsigned g_bars[8][64];                   // per-bt ctr, 256B stride

__device__ __forceinline__ float sigf(float x) { return 1.0f / (1.0f + __expf(-x)); }

// Packed fp32x2 FMA: acc.{lo,hi} += a.{lo,hi} * w.{lo,hi}  (SASS FFMA2)
__device__ __forceinline__ void ffma2(ull& acc, ull a, ull w) {
  asm("fma.rn.f32x2 %0, %1, %2, %0;" : "+l"(acc) : "l"(a), "l"(w));
}
__device__ __forceinline__ ull pack1(float lo) {
  ull r; asm("mov.b64 %0, {%1, %2};" : "=l"(r) : "f"(lo), "f"(0.0f));
  return r;
}
__device__ __forceinline__ float unpack_sum(ull v) {
  float lo, hi;
  asm("mov.b64 {%0, %1}, %2;" : "=f"(lo), "=f"(hi) : "l"(v));
  return lo + hi;
}

// 16(batch) x 64(gatecol) x 256(k) micro-GEMM piece: this thread accumulates
// 2 batch rows x 4 gates with even/odd-k packed accumulators. wb points at
// weight row hl of gate 0; gate g lives at +g*16*WPAD rows.
__device__ __forceinline__ void gemm_tile(const float* __restrict__ wb,
                                          const float* __restrict__ a0p,
                                          const float* __restrict__ a1p,
                                          ull acc[2][4]) {
#pragma unroll 8
  for (int k = 0; k < 256; k += 4) {
    ulonglong2 a0 = *(const ulonglong2*)(a0p + k);   // {k0k1, k2k3}
    ulonglong2 a1 = *(const ulonglong2*)(a1p + k);
#pragma unroll
    for (int g = 0; g < 4; ++g) {
      ulonglong2 w = *(const ulonglong2*)(wb + g * (16 * WPAD) + k);
      ffma2(acc[0][g], a0.x, w.x);
      ffma2(acc[0][g], a0.y, w.y);
      ffma2(acc[1][g], a1.x, w.x);
      ffma2(acc[1][g], a1.y, w.y);
    }
  }
}

// ---------------------------------------------------------------------------
// Prologue: grid = (16 h-tiles, 2048 blocks of 128 flattened (t,b) rows).
// ---------------------------------------------------------------------------
__global__ void __launch_bounds__(NTHR) prologue_kernel(
    const float* __restrict__ x,   const float* __restrict__ h0,
    const float* __restrict__ w_ih, const float* __restrict__ b_ih,
    const float* __restrict__ b_hh) {
  extern __shared__ float sm[];
  float* sW = sm;              // 64 x WPAD
  float* sA = sm + 64 * WPAD;  // 16 x WPAD
  const int tid = threadIdx.x;
  const int ht  = blockIdx.x;

  if (blockIdx.y == 0) {
    if (blockIdx.x == 0 && tid < 8) g_bars[tid][0] = 0u;
    // copy h0[0] (first B*H elements) into buffer 0
    int gtid = blockIdx.x * NTHR + tid;
    for (int i = gtid; i < B_ * H_; i += 16 * NTHR) g_hbuf[0][i] = h0[i];
  }

  // Load w_ih[0] slice, gate-major rows r = g*16 + hl (float4 vectorized).
  for (int idx = tid; idx < 64 * 64; idx += NTHR) {
    int r = idx >> 6, kq = idx & 63;
    int g = r >> 4, hl2 = r & 15;
    int gcol = g * 256 + ht * 16 + hl2;
    *(float4*)&sW[r * WPAD + kq * 4] =
        __ldg((const float4*)(w_ih + (size_t)gcol * IN_) + kq);
  }
  const int hl = tid & 15, bp = tid >> 4;
  float bias[4];
#pragma unroll
  for (int g = 0; g < 4; ++g) {
    int gcol = g * 256 + ht * 16 + hl;
    bias[g] = b_ih[gcol] + b_hh[gcol];
  }
  const float* wb = sW + hl * WPAD;

  for (int sub = 0; sub < 8; ++sub) {
    size_t rows0 = (size_t)blockIdx.y * 128 + sub * 16;
    __syncthreads();  // weights ready (sub 0) / previous GEMM readers done
    const float4* xs = (const float4*)(x + rows0 * IN_);
    for (int idx = tid; idx < 16 * 64; idx += NTHR) {
      int rr = idx >> 6, kq = idx & 63;
      *(float4*)&sA[rr * WPAD + kq * 4] = __ldg(xs + rr * 64 + kq);
    }
    __syncthreads();
    ull acc[2][4];
#pragma unroll
    for (int g = 0; g < 4; ++g) { acc[0][g] = pack1(bias[g]); acc[1][g] = pack1(bias[g]); }
    gemm_tile(wb, sA + (2 * bp) * WPAD, sA + (2 * bp + 1) * WPAD, acc);
#pragma unroll
    for (int bi = 0; bi < 2; ++bi) {
      size_t r = rows0 + 2 * bp + bi;
      float4 v = make_float4(unpack_sum(acc[bi][0]), unpack_sum(acc[bi][1]),
                             unpack_sum(acc[bi][2]), unpack_sum(acc[bi][3]));
      __stcs((float4*)&g_P[r * GH_ + ht * 64 + hl * 4], v);
    }
  }
}

// Per-bt barrier (16 CTAs). Arrive publishes this CTA's global writes;
// wait acquire-polls. Work placed between arrive and wait overlaps the skew.
__device__ __forceinline__ void bar_arrive(unsigned* ctr) {
  __syncthreads();
  if (threadIdx.x == 0) {
    __threadfence();
    atomicAdd(ctr, 1u);
  }
}
__device__ __forceinline__ void bar_wait(unsigned* ctr, unsigned target) {
  if (threadIdx.x == 0) {
    unsigned v;
    do {
      asm volatile("ld.acquire.gpu.b32 %0, [%1];" : "=r"(v) : "l"(ctr) : "memory");
    } while (v < target);
  }
  __syncthreads();
}

// ---------------------------------------------------------------------------
// Persistent recurrent kernel: 128 CTAs (8 bt x 16 ht) x 128 threads.
// Thread (hl = tid&15, bp = tid>>4) owns cells (b0, hglob), (b0+1, hglob)
// with b0 = bt*16 + 2*bp, hglob = ht*16 + hl; c-state in registers.
// ---------------------------------------------------------------------------
__global__ void __launch_bounds__(NTHR, 1) lstm_kernel(
    const float* __restrict__ c0,
    const float* __restrict__ w_ih, const float* __restrict__ b_ih,
    const float* __restrict__ w_hh, const float* __restrict__ b_hh,
    float* __restrict__ out) {
  extern __shared__ float sm[];
  float* sW0 = sm;               // layer-0 w_hh slice, 64 x WPAD
  float* sW1 = sm + 64 * WPAD;   // layer-1 (w_ih1+w_hh1) slice, 64 x WPAD
  float* sA  = sm + 128 * WPAD;  // h staging, 16 x WPAD
  const int tid = threadIdx.x;
  const int bt  = blockIdx.x >> 4;   // 0..7
  const int ht  = blockIdx.x & 15;   // 0..15
  const int hl  = tid & 15, bp = tid >> 4;
  const int b0  = bt * 16 + 2 * bp;
  const int hglob = ht * 16 + hl;
  unsigned* ctr = &g_bars[bt][0];

  // Resident weights (loaded once). Gate-major rows r = g*16 + hl2.
  for (int idx = tid; idx < 64 * 64; idx += NTHR) {
    int r = idx >> 6, kq = idx & 63;
    int g = r >> 4, hl2 = r & 15;
    int gcol = g * 256 + ht * 16 + hl2;
    float4 w0 = __ldg((const float4*)(w_hh + (size_t)gcol * H_) + kq);
    *(float4*)&sW0[r * WPAD + kq * 4] = w0;
    float4 wa = __ldg((const float4*)(w_ih + (size_t)(GH_ + gcol) * IN_) + kq);
    float4 wb4 = __ldg((const float4*)(w_hh + (size_t)(GH_ + gcol) * H_) + kq);
    *(float4*)&sW1[r * WPAD + kq * 4] =
        make_float4(wa.x + wb4.x, wa.y + wb4.y, wa.z + wb4.z, wa.w + wb4.w);
  }
  float bias1[4];
#pragma unroll
  for (int g = 0; g < 4; ++g) {
    int gcol = g * 256 + ht * 16 + hl;
    bias1[g] = b_ih[GH_ + gcol] + b_hh[GH_ + gcol];
  }
  const float* wb0 = sW0 + hl * WPAD;
  const float* wb1 = sW1 + hl * WPAD;
  const float* a0p = sA + (2 * bp) * WPAD;
  const float* a1p = a0p + WPAD;

  float c[2];
#pragma unroll
  for (int bi = 0; bi < 2; ++bi) c[bi] = c0[(size_t)(b0 + bi) * H_ + hglob];

  // Prefetch P[0] (streaming, hides DRAM latency behind weight loads).
  float4 p0, p1;
  {
    size_t base = ((size_t)0 * B_ + b0) * GH_ + ht * 64 + hl * 4;
    p0 = __ldcs((const float4*)&g_P[base]);
    p1 = __ldcs((const float4*)&g_P[base + GH_]);
  }

  unsigned target = 16;

  for (int t = 0; t < S_; ++t) {
    // ---------------- Phase A: layer 0 (reads buf0, writes buf1) ----------
    for (int idx = tid; idx < 16 * 64; idx += NTHR) {
      int rr = idx >> 6, kq = idx & 63;
      *(float4*)&sA[rr * WPAD + kq * 4] =
          __ldcg((const float4*)&g_hbuf[0][(size_t)(bt * 16 + rr) * H_] + kq);
    }
    __syncthreads();
    {
      ull acc[2][4] = {{pack1(p0.x), pack1(p0.y), pack1(p0.z), pack1(p0.w)},
                       {pack1(p1.x), pack1(p1.y), pack1(p1.z), pack1(p1.w)}};
      gemm_tile(wb0, a0p, a1p, acc);
#pragma unroll
      for (int bi = 0; bi < 2; ++bi) {
        float ig = unpack_sum(acc[bi][0]), fg = unpack_sum(acc[bi][1]);
        float cg = unpack_sum(acc[bi][2]), og = unpack_sum(acc[bi][3]);
        c[bi] = sigf(fg) * c[bi] + sigf(ig) * fmaxf(cg, 0.0f);
        float h = sigf(og) * fmaxf(c[bi], 0.0f);
        __stcg(&g_hbuf[1][(size_t)(b0 + bi) * H_ + hglob], h);
        if (t == S_ - 1) {
          out[HY_OFF + (size_t)(b0 + bi) * H_ + hglob] = h;
          out[CY_OFF + (size_t)(b0 + bi) * H_ + hglob] = c[bi];
        }
      }
    }
    bar_arrive(ctr);
    bar_wait(ctr, target); target += 16;

    // ---------------- Phase B: layer 1 (reads buf1, writes buf0) ----------
    for (int idx = tid; idx < 16 * 64; idx += NTHR) {
      int rr = idx >> 6, kq = idx & 63;
      *(float4*)&sA[rr * WPAD + kq * 4] =
          __ldcg((const float4*)&g_hbuf[1][(size_t)(bt * 16 + rr) * H_] + kq);
    }
    __syncthreads();
    {
      ull acc[2][4] = {{pack1(bias1[0]), pack1(bias1[1]), pack1(bias1[2]), pack1(bias1[3])},
                       {pack1(bias1[0]), pack1(bias1[1]), pack1(bias1[2]), pack1(bias1[3])}};
      gemm_tile(wb1, a0p, a1p, acc);
      float hv[2];
#pragma unroll
      for (int bi = 0; bi < 2; ++bi) {
        float ig = unpack_sum(acc[bi][0]), fg = unpack_sum(acc[bi][1]);
        float cg = unpack_sum(acc[bi][2]), og = unpack_sum(acc[bi][3]);
        c[bi] = sigf(fg) * c[bi] + sigf(ig) * fmaxf(cg, 0.0f);
        float h = sigf(og) * fmaxf(c[bi], 0.0f);
        hv[bi] = h;
        __stcg(&g_hbuf[0][(size_t)(b0 + bi) * H_ + hglob], h);
      }
      bar_arrive(ctr);
      // Overlap inside the barrier window: out stores + next-step P prefetch.
#pragma unroll
      for (int bi = 0; bi < 2; ++bi) {
        __stcs(&out[(size_t)t * B_ * H_ + (size_t)(b0 + bi) * H_ + hglob], hv[bi]);
        if (t == S_ - 1) {
          out[HY_OFF + (size_t)B_ * H_ + (size_t)(b0 + bi) * H_ + hglob] = hv[bi];
          out[CY_OFF + (size_t)B_ * H_ + (size_t)(b0 + bi) * H_ + hglob] = c[bi];
        }
      }
      if (t + 1 < S_) {
        size_t base = ((size_t)(t + 1) * B_ + b0) * GH_ + ht * 64 + hl * 4;
        p0 = __ldcs((const float4*)&g_P[base]);
        p1 = __ldcs((const float4*)&g_P[base + GH_]);
      }
      bar_wait(ctr, target); target += 16;
    }
  }
}

extern "C" void kernel_launch(void* const* d_in, const int* in_sizes, int n_in,
                              void* d_out, int out_size) {
  const float* x    = (const float*)d_in[0];
  const float* h0   = (const float*)d_in[1];
  const float* c0   = (const float*)d_in[2];
  const float* w_ih = (const float*)d_in[3];
  const float* b_ih = (const float*)d_in[4];
  const float* w_hh = (const float*)d_in[5];
  const float* b_hh = (const float*)d_in[6];
  float* out = (float*)d_out;

  const int PRO_SMEM  = 80  * WPAD * sizeof(float);   //  83,200 B
  const int LSTM_SMEM = 144 * WPAD * sizeof(float);   // 149,760 B
  static bool attr_done = false;
  if (!attr_done) {
    cudaFuncSetAttribute(prologue_kernel,
                         cudaFuncAttributeMaxDynamicSharedMemorySize, PRO_SMEM);
    cudaFuncSetAttribute(lstm_kernel,
                         cudaFuncAttributeMaxDynamicSharedMemorySize, LSTM_SMEM);
    attr_done = true;
  }

  dim3 pgrid(16, (S_ * B_) / 128);  // (h-tiles, 128-row blocks)
  prologue_kernel<<<pgrid, NTHR, PRO_SMEM>>>(x, h0, w_ih, b_ih, b_hh);
  lstm_kernel<<<NCTA, NTHR, LSTM_SMEM>>>(c0, w_ih, b_ih, w_hh, b_hh, out);
}

// round 8
// speedup vs baseline: 1.0753x; 1.0657x over previous
#include <cuda_runtime.h>
#include <cstdint>
#include <cstddef>

// ---------------------------------------------------------------------------
// ReLU-LSTM: S=2048, B=128, H=256, IN=256, L=2; one (h,c) state threads
// through both layers and time.
//
//   prologue_kernel: P[t,b,:] = x_t @ w_ih0^T + b_ih0 + b_hh0 (all t parallel),
//                    stored as P[row][ht*64 + r] with gate-row r = g*16 + hv.
//   lstm_kernel:     persistent 128-CTA x 256-thread kernel; 2048 steps x 2
//                    layer phases. Layer 1 uses W1 = w_ih1 + w_hh1.
//
// R8: 4rowsx2gates mapping (W LDS fully 32-distinct, A warp-uniform
// broadcast), 256 threads with k-split + SMEM reduction, red.release
// barrier arrive, rcp.approx sigmoid.
// ---------------------------------------------------------------------------

#define S_    2048
#define B_    128
#define H_    256
#define IN_   256
#define GH_   1024        // 4*H gate columns
#define NCTA  128         // 8 batch-tiles x 16 h-tiles
#define NTHR  256
#define PNTHR 128
#define WPAD  260         // padded row stride (floats), 1040 B (16B aligned)

#define OUT_Y  ((size_t)S_ * B_ * H_)
#define HY_OFF (OUT_Y)
#define CY_OFF (OUT_Y + 2ull * B_ * H_)

typedef unsigned long long ull;

__device__ float    g_P[(size_t)S_ * B_ * GH_];      // precomputed x-proj
__device__ float    g_hbuf[2][B_ * H_];              // double-buffered h
__device__ unsigned g_bars[8][64];                   // per-bt ctr, 256B stride

__device__ __forceinline__ float sigf(float x) {
  float e = __expf(-x);
  float d = 1.0f + e;
  float r;
  asm("rcp.approx.f32 %0, %1;" : "=f"(r) : "f"(d));
  return r;
}

// Packed fp32x2 FMA (SASS FFMA2): acc.{lo,hi} += a.{lo,hi} * w.{lo,hi}
__device__ __forceinline__ void ffma2(ull& acc, ull a, ull w) {
  asm("fma.rn.f32x2 %0, %1, %2, %0;" : "+l"(acc) : "l"(a), "l"(w));
}
__device__ __forceinline__ ull pack1(float lo) {
  ull r; asm("mov.b64 %0, {%1, %2};" : "=l"(r) : "f"(lo), "f"(0.0f));
  return r;
}
__device__ __forceinline__ float unpack_sum(ull v) {
  float lo, hi;
  asm("mov.b64 {%0, %1}, %2;" : "=f"(lo), "=f"(hi) : "l"(v));
  return lo + hi;
}

// ---------------------------------------------------------------------------
// Prologue: grid = (16 h-tiles, 1024 blocks of 256 (t,b) rows), 128 threads.
// Thread (hl = tid&31, bq = tid>>5): 8 rows x 2 gate-rows (hl, hl+32).
// ---------------------------------------------------------------------------
__global__ void __launch_bounds__(PNTHR) prologue_kernel(
    const float* __restrict__ x,    const float* __restrict__ h0,
    const float* __restrict__ w_ih, const float* __restrict__ b_ih,
    const float* __restrict__ b_hh) {
  extern __shared__ float sm[];
  float* sW = sm;              // 64 x WPAD
  float* sA = sm + 64 * WPAD;  // 32 x WPAD
  const int tid = threadIdx.x;
  const int ht  = blockIdx.x;

  if (blockIdx.y == 0) {
    if (blockIdx.x == 0 && tid < 8) g_bars[tid][0] = 0u;
    for (int i = blockIdx.x * PNTHR + tid; i < B_ * H_; i += 16 * PNTHR)
      g_hbuf[0][i] = h0[i];
  }

  // W rows r = g*16 + hv -> gate column g*256 + ht*16 + hv.
  for (int idx = tid; idx < 64 * 64; idx += PNTHR) {
    int r = idx >> 6, kq = idx & 63;
    int g = r >> 4, hv = r & 15;
    int gcol = g * 256 + ht * 16 + hv;
    *(float4*)&sW[r * WPAD + kq * 4] =
        __ldg((const float4*)(w_ih + (size_t)gcol * IN_) + kq);
  }
  const int hl = tid & 31, bq = tid >> 5;
  float bias[2];
#pragma unroll
  for (int gi = 0; gi < 2; ++gi) {
    int r = hl + gi * 32;
    int gcol = (r >> 4) * 256 + ht * 16 + (r & 15);
    bias[gi] = b_ih[gcol] + b_hh[gcol];
  }
  const float* w0p = sW + hl * WPAD;
  const float* w1p = sW + (hl + 32) * WPAD;
  const float* aB  = sA + (bq * 8) * WPAD;

  for (int sub = 0; sub < 8; ++sub) {
    size_t rows0 = (size_t)blockIdx.y * 256 + sub * 32;
    __syncthreads();  // weights ready (sub 0) / prior GEMM readers done
    for (int idx = tid; idx < 32 * 64; idx += PNTHR) {
      int rr = idx >> 6, kq = idx & 63;
      *(float4*)&sA[rr * WPAD + kq * 4] =
          __ldg((const float4*)(x + (rows0 + rr) * IN_) + kq);
    }
    __syncthreads();
    ull acc[8][2];
#pragma unroll
    for (int j = 0; j < 8; ++j) {
      acc[j][0] = pack1(bias[0]); acc[j][1] = pack1(bias[1]);
    }
#pragma unroll 4
    for (int k = 0; k < 256; k += 4) {
      ulonglong2 w0 = *(const ulonglong2*)(w0p + k);
      ulonglong2 w1 = *(const ulonglong2*)(w1p + k);
#pragma unroll
      for (int j = 0; j < 8; ++j) {
        ulonglong2 a = *(const ulonglong2*)(aB + j * WPAD + k);
        ffma2(acc[j][0], a.x, w0.x); ffma2(acc[j][0], a.y, w0.y);
        ffma2(acc[j][1], a.x, w1.x); ffma2(acc[j][1], a.y, w1.y);
      }
    }
#pragma unroll
    for (int j = 0; j < 8; ++j) {
      size_t row = rows0 + bq * 8 + j;
      size_t base = row * GH_ + ht * 64;
      __stcs(&g_P[base + hl],      unpack_sum(acc[j][0]));
      __stcs(&g_P[base + hl + 32], unpack_sum(acc[j][1]));
    }
  }
}

// Per-bt 16-CTA barrier: release-red publishes prior writes (after CTA-wide
// syncthreads); acquire-poll observes.
__device__ __forceinline__ void bar_arrive(unsigned* ctr) {
  __syncthreads();
  if (threadIdx.x == 0) {
    asm volatile("red.release.gpu.global.add.u32 [%0], %1;"
                 :: "l"(ctr), "r"(1u) : "memory");
  }
}
__device__ __forceinline__ void bar_wait(unsigned* ctr, unsigned target) {
  if (threadIdx.x == 0) {
    unsigned v;
    do {
      asm volatile("ld.acquire.gpu.b32 %0, [%1];" : "=r"(v) : "l"(ctr) : "memory");
    } while (v < target);
  }
  __syncthreads();
}

// ---------------------------------------------------------------------------
// Persistent recurrent kernel: 128 CTAs (8 bt x 16 ht) x 256 threads.
// Warp w: hl = tid&31 (gate-row pair), bq = w&3 (4 batch rows), grp = w>>2
// (k-half). Group-0 threads with hl>=16 own c-state for (b, hglob).
// ---------------------------------------------------------------------------
__global__ void __launch_bounds__(NTHR, 1) lstm_kernel(
    const float* __restrict__ c0,
    const float* __restrict__ w_ih, const float* __restrict__ b_ih,
    const float* __restrict__ w_hh, const float* __restrict__ b_hh,
    float* __restrict__ out) {
  extern __shared__ float sm[];
  float* sW0  = sm;                // 64 x WPAD
  float* sW1  = sm + 64 * WPAD;    // 64 x WPAD
  float* sA   = sm + 128 * WPAD;   // 16 x WPAD
  float* sRed = sm + 144 * WPAD;   // 1024 floats (k-split partials)
  const int tid = threadIdx.x;
  const int bt  = blockIdx.x >> 4;
  const int ht  = blockIdx.x & 15;
  const int hl  = tid & 31;
  const int wid = tid >> 5;
  const int bq  = wid & 3;
  const int grp = wid >> 2;        // 0: k<128 (+epilogue), 1: k>=128
  const int kb  = grp * 128;
  const int hv  = hl & 15;
  const int br0 = bq * 4;
  const int bglob0 = bt * 16 + br0;
  const int hglob  = ht * 16 + hv;
  const bool isB = (hl >= 16);
  unsigned* ctr = &g_bars[bt][0];

  // Resident weights: rows r = g*16 + hv.
  for (int idx = tid; idx < 64 * 64; idx += NTHR) {
    int r = idx >> 6, kq = idx & 63;
    int g = r >> 4, hv2 = r & 15;
    int gcol = g * 256 + ht * 16 + hv2;
    *(float4*)&sW0[r * WPAD + kq * 4] =
        __ldg((const float4*)(w_hh + (size_t)gcol * H_) + kq);
    float4 wa = __ldg((const float4*)(w_ih + (size_t)(GH_ + gcol) * IN_) + kq);
    float4 wb = __ldg((const float4*)(w_hh + (size_t)(GH_ + gcol) * H_) + kq);
    *(float4*)&sW1[r * WPAD + kq * 4] =
        make_float4(wa.x + wb.x, wa.y + wb.y, wa.z + wb.z, wa.w + wb.w);
  }
  float bias1[2];
#pragma unroll
  for (int gi = 0; gi < 2; ++gi) {
    int r = hl + gi * 32;
    int gcol = (r >> 4) * 256 + ht * 16 + (r & 15);
    bias1[gi] = b_ih[GH_ + gcol] + b_hh[GH_ + gcol];
  }
  const float* w0p = sW0 + hl * WPAD;
  const float* w0q = sW0 + (hl + 32) * WPAD;
  const float* w1p = sW1 + hl * WPAD;
  const float* w1q = sW1 + (hl + 32) * WPAD;
  const float* aB  = sA + br0 * WPAD;

  float c[4];
#pragma unroll
  for (int j = 0; j < 4; ++j)
    c[j] = c0[(size_t)(bglob0 + j) * H_ + hglob];

  // Prefetch P[0] (group 0 only uses it).
  float pr[4][2];
  if (grp == 0) {
#pragma unroll
    for (int j = 0; j < 4; ++j) {
      size_t base = ((size_t)0 * B_ + bglob0 + j) * GH_ + ht * 64;
      pr[j][0] = __ldcs(&g_P[base + hl]);
      pr[j][1] = __ldcs(&g_P[base + hl + 32]);
    }
  }

  unsigned target = 16;

  for (int t = 0; t < S_; ++t) {
#pragma unroll 1
    for (int phase = 0; phase < 2; ++phase) {
      const int src = phase, dst = phase ^ 1;
      // ---- stage h tile ----
      for (int idx = tid; idx < 16 * 64; idx += NTHR) {
        int rr = idx >> 6, kq = idx & 63;
        *(float4*)&sA[rr * WPAD + kq * 4] =
            __ldcg((const float4*)&g_hbuf[src][(size_t)(bt * 16 + rr) * H_] + kq);
      }
      __syncthreads();
      // ---- GEMM (k-split across warp groups) ----
      ull acc[4][2];
      if (grp == 0) {
        if (phase == 0) {
#pragma unroll
          for (int j = 0; j < 4; ++j) {
            acc[j][0] = pack1(pr[j][0]); acc[j][1] = pack1(pr[j][1]);
          }
        } else {
#pragma unroll
          for (int j = 0; j < 4; ++j) {
            acc[j][0] = pack1(bias1[0]); acc[j][1] = pack1(bias1[1]);
          }
        }
      } else {
#pragma unroll
        for (int j = 0; j < 4; ++j) { acc[j][0] = 0ull; acc[j][1] = 0ull; }
      }
      const float* wp = (phase == 0) ? w0p : w1p;
      const float* wq = (phase == 0) ? w0q : w1q;
#pragma unroll 4
      for (int k4 = 0; k4 < 128; k4 += 4) {
        int k = kb + k4;
        ulonglong2 w0 = *(const ulonglong2*)(wp + k);
        ulonglong2 w1 = *(const ulonglong2*)(wq + k);
#pragma unroll
        for (int j = 0; j < 4; ++j) {
          ulonglong2 a = *(const ulonglong2*)(aB + j * WPAD + k);
          ffma2(acc[j][0], a.x, w0.x); ffma2(acc[j][0], a.y, w0.y);
          ffma2(acc[j][1], a.x, w1.x); ffma2(acc[j][1], a.y, w1.y);
        }
      }
      // ---- reduce k-halves ----
      if (grp == 1) {
#pragma unroll
        for (int j = 0; j < 4; ++j) {
          sRed[(br0 + j) * 64 + hl]      = unpack_sum(acc[j][0]);
          sRed[(br0 + j) * 64 + 32 + hl] = unpack_sum(acc[j][1]);
        }
      }
      __syncthreads();
      // ---- epilogue (group 0) ----
      if (grp == 0) {
        float hvout[4];
#pragma unroll
        for (int j = 0; j < 4; ++j) {
          float g0 = unpack_sum(acc[j][0]) + sRed[(br0 + j) * 64 + hl];
          float g1 = unpack_sum(acc[j][1]) + sRed[(br0 + j) * 64 + 32 + hl];
          // hl<16: g0=ig, g1=cg.   hl>=16: g0=fg, g1=og.
          float s0 = sigf(g0);
          float u  = s0 * fmaxf(g1, 0.0f);          // A-threads: sig(ig)*relu(cg)
          float uin = __shfl_xor_sync(0xFFFFFFFFu, u, 16);
          if (isB) {
            c[j] = s0 * c[j] + uin;                 // sig(fg)*c + uin
            float h = sigf(g1) * fmaxf(c[j], 0.0f); // sig(og)*relu(c)
            hvout[j] = h;
            __stcg(&g_hbuf[dst][(size_t)(bglob0 + j) * H_ + hglob], h);
            if (t == S_ - 1) {
              size_t lo = (size_t)phase * B_ * H_ + (size_t)(bglob0 + j) * H_ + hglob;
              out[HY_OFF + lo] = h;
              out[CY_OFF + lo] = c[j];
            }
          }
        }
        bar_arrive(ctr);
        // Inside the barrier window: out stores + next-step P prefetch.
        if (phase == 1) {
          if (isB) {
#pragma unroll
            for (int j = 0; j < 4; ++j)
              __stcs(&out[(size_t)t * B_ * H_ + (size_t)(bglob0 + j) * H_ + hglob],
                     hvout[j]);
          }
          if (t + 1 < S_) {
#pragma unroll
            for (int j = 0; j < 4; ++j) {
              size_t base = ((size_t)(t + 1) * B_ + bglob0 + j) * GH_ + ht * 64;
              pr[j][0] = __ldcs(&g_P[base + hl]);
              pr[j][1] = __ldcs(&g_P[base + hl + 32]);
            }
          }
        }
      } else {
        bar_arrive(ctr);
      }
      bar_wait(ctr, target); target += 16;
    }
  }
}

extern "C" void kernel_launch(void* const* d_in, const int* in_sizes, int n_in,
                              void* d_out, int out_size) {
  const float* x    = (const float*)d_in[0];
  const float* h0   = (const float*)d_in[1];
  const float* c0   = (const float*)d_in[2];
  const float* w_ih = (const float*)d_in[3];
  const float* b_ih = (const float*)d_in[4];
  const float* w_hh = (const float*)d_in[5];
  const float* b_hh = (const float*)d_in[6];
  float* out = (float*)d_out;

  const int PRO_SMEM  = 96 * WPAD * sizeof(float);                 //  99,840 B
  const int LSTM_SMEM = (144 * WPAD + 1024) * sizeof(float);       // 153,856 B
  static bool attr_done = false;
  if (!attr_done) {
    cudaFuncSetAttribute(prologue_kernel,
                         cudaFuncAttributeMaxDynamicSharedMemorySize, PRO_SMEM);
    cudaFuncSetAttribute(lstm_kernel,
                         cudaFuncAttributeMaxDynamicSharedMemorySize, LSTM_SMEM);
    attr_done = true;
  }

  dim3 pgrid(16, (S_ * B_) / 256);  // (h-tiles, 256-row blocks)
  prologue_kernel<<<pgrid, PNTHR, PRO_SMEM>>>(x, h0, w_ih, b_ih, b_hh);
  lstm_kernel<<<NCTA, NTHR, LSTM_SMEM>>>(c0, w_ih, b_ih, w_hh, b_hh, out);
}